// round 5
// baseline (speedup 1.0000x reference)
#include <cuda_runtime.h>

#define V_VOCAB 500000
#define D 128
#define M_MEM 1000
#define L_MEM 64
#define L_X 64
#define C_N 100
#define L_C 32
#define L_Y 32
#define N_MEMS (M_MEM + 1)            /* 1001: row0=xs, rows1..1000=mems */
#define OUT_ROWS (1 + C_N)            /* 101 */
#define MAX_NORM 10.0f
#define RENORM_EPS 1e-7f
#define COS_EPS 1e-8f

// Scratch: row 0 = xs encoding, rows 1..1000 = mems encodings. 512.5 KB.
__device__ float g_enc[(size_t)N_MEMS * D];

// ---------------------------------------------------------------------------
// Encode body, L compile-time. 256 threads = 8 warps; warp w owns tokens
// w, w+8, ... All NT row gathers in flight at once; the NT norm reduces are
// explicitly interleaved so the shuffle chains pipeline instead of
// serializing (~170 cyc instead of ~NT*140).
// ---------------------------------------------------------------------------
template <int L>
__device__ __forceinline__ void encode_body(
    const int* __restrict__ seq,
    const float* __restrict__ lt, const float* __restrict__ freqs,
    float* __restrict__ dst)
{
    constexpr int NT = L / 8;

    __shared__ int   sh_idx[L];
    __shared__ float sh_w[L];
    __shared__ float sh_wred[2];
    __shared__ float sh_acc[8][D];

    int tid  = threadIdx.x;
    int warp = tid >> 5;
    int lane = tid & 31;

    if (tid < L) {
        int idx = seq[tid];
        sh_idx[tid] = idx;
        float f = freqs[idx];
        sh_w[tid] = f;
        float ws = f * f;
        #pragma unroll
        for (int o = 16; o > 0; o >>= 1)
            ws += __shfl_xor_sync(0xffffffffu, ws, o);
        if (lane == 0) sh_wred[warp] = ws;
    }
    __syncthreads();

    float inv_wnorm = rsqrtf((L > 32) ? (sh_wred[0] + sh_wred[1]) : sh_wred[0]);

    // all NT row gathers in flight
    float4 e[NT];
    int    tok[NT];
    #pragma unroll
    for (int k = 0; k < NT; k++) {
        tok[k] = warp + 8 * k;
        int idx = sh_idx[tok[k]];
        e[k] = *reinterpret_cast<const float4*>(lt + (size_t)idx * D + lane * 4);
    }

    // interleaved norm reduces
    float sq[NT];
    #pragma unroll
    for (int k = 0; k < NT; k++)
        sq[k] = e[k].x * e[k].x + e[k].y * e[k].y
              + e[k].z * e[k].z + e[k].w * e[k].w;
    #pragma unroll
    for (int o = 16; o > 0; o >>= 1) {
        #pragma unroll
        for (int k = 0; k < NT; k++)
            sq[k] += __shfl_xor_sync(0xffffffffu, sq[k], o);
    }

    float4 acc = make_float4(0.0f, 0.0f, 0.0f, 0.0f);
    #pragma unroll
    for (int k = 0; k < NT; k++) {
        float n = sqrtf(sq[k]);
        float scale = (n > MAX_NORM) ? (MAX_NORM / (n + RENORM_EPS)) : 1.0f;
        float wl = sh_w[tok[k]] * inv_wnorm * scale;
        acc.x += wl * e[k].x;
        acc.y += wl * e[k].y;
        acc.z += wl * e[k].z;
        acc.w += wl * e[k].w;
    }

    sh_acc[warp][lane * 4 + 0] = acc.x;
    sh_acc[warp][lane * 4 + 1] = acc.y;
    sh_acc[warp][lane * 4 + 2] = acc.z;
    sh_acc[warp][lane * 4 + 3] = acc.w;
    __syncthreads();

    if (tid < D) {
        float s = 0.0f;
        #pragma unroll
        for (int w = 0; w < 8; w++) s += sh_acc[w][tid];
        dst[tid] = s;
    }
}

// ---------------------------------------------------------------------------
// Kernel A: encode all 1102 sequences (fully independent).
// ---------------------------------------------------------------------------
__global__ __launch_bounds__(256) void encode_all(
    const int* __restrict__ xs, const int* __restrict__ mems,
    const int* __restrict__ ys, const int* __restrict__ cands,
    const float* __restrict__ lt, const float* __restrict__ freqs,
    float* __restrict__ out)
{
    int b = blockIdx.x;
    if (b == 0) {
        encode_body<L_X>(xs, lt, freqs, g_enc);
    } else if (b <= M_MEM) {
        encode_body<L_MEM>(mems + (size_t)(b - 1) * L_MEM, lt, freqs,
                           g_enc + (size_t)b * D);
    } else if (b == M_MEM + 1) {
        encode_body<L_Y>(ys, lt, freqs, out + (size_t)OUT_ROWS * D);
    } else {
        int c = b - M_MEM - 2;
        encode_body<L_C>(cands + (size_t)c * L_C, lt, freqs,
                         out + (size_t)(OUT_ROWS + 1 + c) * D);
    }
}

// ---------------------------------------------------------------------------
// Kernel B: fused sims + softmax + weighted sum + outputs. 1024 threads.
// Sims: 32 warps x 4 batches of 8 rows: 8 independent L2 row loads, then
// interleaved reduce rounds (latency paid once per batch, not per row).
// ---------------------------------------------------------------------------
__global__ __launch_bounds__(1024) void finalize_kernel(float* __restrict__ out)
{
    __shared__ float sh_x[D];
    __shared__ float sims[N_MEMS];
    __shared__ float red[32];
    __shared__ float sh_stat[2];
    __shared__ float part[32][D];
    __shared__ float sh_lhs[D];

    int tid  = threadIdx.x;
    int warp = tid >> 5;
    int lane = tid & 31;

    if (tid < D) sh_x[tid] = g_enc[tid];
    __syncthreads();

    float4 x4 = *reinterpret_cast<const float4*>(&sh_x[lane * 4]);

    // per-warp xs normsq (redundant across warps; avoids a block sync)
    float xsq = x4.x * x4.x + x4.y * x4.y + x4.z * x4.z + x4.w * x4.w;
    #pragma unroll
    for (int o = 16; o > 0; o >>= 1)
        xsq += __shfl_xor_sync(0xffffffffu, xsq, o);
    float nx = fmaxf(sqrtf(xsq), COS_EPS);

    // --- sims: batches of 8 rows per warp ---
    #pragma unroll
    for (int jb = 0; jb < 4; jb++) {
        int i0 = jb * 256 + warp;                  // + k*32
        float4 e[8];
        #pragma unroll
        for (int k = 0; k < 8; k++) {
            int i = i0 + k * 32;
            int r = (i < M_MEM) ? (i + 1) : 0;     // i==1000 -> row 0 (xs)
            bool valid = (i < N_MEMS);
            const float4* row = reinterpret_cast<const float4*>(
                &g_enc[(size_t)(valid ? r : 0) * D]);
            e[k] = row[lane];
        }
        float dot[8], sqv[8];
        #pragma unroll
        for (int k = 0; k < 8; k++) {
            dot[k] = e[k].x * x4.x + e[k].y * x4.y + e[k].z * x4.z + e[k].w * x4.w;
            sqv[k] = e[k].x * e[k].x + e[k].y * e[k].y + e[k].z * e[k].z + e[k].w * e[k].w;
        }
        #pragma unroll
        for (int o = 16; o > 0; o >>= 1) {
            #pragma unroll
            for (int k = 0; k < 8; k++) {
                dot[k] += __shfl_xor_sync(0xffffffffu, dot[k], o);
                sqv[k] += __shfl_xor_sync(0xffffffffu, sqv[k], o);
            }
        }
        if (lane == 0) {
            #pragma unroll
            for (int k = 0; k < 8; k++) {
                int i = i0 + k * 32;
                if (i < N_MEMS) {
                    float nm = fmaxf(sqrtf(sqv[k]), COS_EPS);
                    sims[i] = dot[k] / (nx * nm);
                }
            }
        }
    }
    __syncthreads();

    // --- softmax max ---
    float lmx = (tid < N_MEMS) ? sims[tid] : -1e30f;
    #pragma unroll
    for (int o = 16; o > 0; o >>= 1)
        lmx = fmaxf(lmx, __shfl_xor_sync(0xffffffffu, lmx, o));
    if (lane == 0) red[warp] = lmx;
    __syncthreads();
    if (tid == 0) {
        float m = red[0];
        #pragma unroll
        for (int w = 1; w < 32; w++) m = fmaxf(m, red[w]);
        sh_stat[0] = m;
    }
    __syncthreads();
    float mx = sh_stat[0];

    // --- exp + sum ---
    float lsum = 0.0f;
    for (int i = tid; i < N_MEMS; i += 1024) {
        float e = expf(sims[i] - mx);
        sims[i] = e;
        lsum += e;
    }
    #pragma unroll
    for (int o = 16; o > 0; o >>= 1)
        lsum += __shfl_xor_sync(0xffffffffu, lsum, o);
    if (lane == 0) red[warp] = lsum;
    __syncthreads();
    if (tid == 0) {
        float s = 0.0f;
        #pragma unroll
        for (int w = 0; w < 32; w++) s += red[w];
        sh_stat[1] = s;
    }
    __syncthreads();
    float inv_sum = 1.0f / sh_stat[1];

    // --- weighted sum: 32 i-chunks x 32 float4-lanes, independent loads ---
    {
        int q = tid & 31;
        int chunk = tid >> 5;
        float4 acc = make_float4(0.0f, 0.0f, 0.0f, 0.0f);
        for (int i = chunk; i < N_MEMS; i += 32) {
            int r = (i < M_MEM) ? (i + 1) : 0;
            float4 e = *reinterpret_cast<const float4*>(&g_enc[(size_t)r * D + q * 4]);
            float w = sims[i];
            acc.x += w * e.x;
            acc.y += w * e.y;
            acc.z += w * e.z;
            acc.w += w * e.w;
        }
        part[chunk][q * 4 + 0] = acc.x;
        part[chunk][q * 4 + 1] = acc.y;
        part[chunk][q * 4 + 2] = acc.z;
        part[chunk][q * 4 + 3] = acc.w;
    }
    __syncthreads();

    if (tid < D) {
        float s = 0.0f;
        #pragma unroll
        for (int c = 0; c < 32; c++) s += part[c][tid];
        sh_lhs[tid] = s * inv_sum;
    }
    __syncthreads();

    // --- broadcast lhs to the 101 xs_out rows ---
    for (int j = tid; j < OUT_ROWS * D; j += 1024)
        out[j] = sh_lhs[j & (D - 1)];
}

extern "C" void kernel_launch(void* const* d_in, const int* in_sizes, int n_in,
                              void* d_out, int out_size) {
    const int*   xs    = (const int*)d_in[0];
    const int*   mems  = (const int*)d_in[1];
    const int*   ys    = (const int*)d_in[2];
    const int*   cands = (const int*)d_in[3];
    const float* lt    = (const float*)d_in[4];
    const float* freqs = (const float*)d_in[5];
    float* out = (float*)d_out;

    encode_all<<<2 + M_MEM + C_N, 256>>>(xs, mems, ys, cands, lt, freqs, out);
    finalize_kernel<<<1, 1024>>>(out);
}

// round 6
// speedup vs baseline: 1.1692x; 1.1692x over previous
#include <cuda_runtime.h>

#define V_VOCAB 500000
#define D 128
#define M_MEM 1000
#define L_MEM 64
#define L_X 64
#define C_N 100
#define L_C 32
#define L_Y 32
#define N_MEMS (M_MEM + 1)            /* 1001: row0=xs, rows1..1000=mems */
#define OUT_ROWS (1 + C_N)            /* 101 */
#define NBLK_B 126                    /* ceil(1001/8) */
#define MAX_NORM 10.0f
#define RENORM_EPS 1e-7f
#define COS_EPS 1e-8f

// Scratch: row 0 = xs encoding, rows 1..1000 = mems encodings. 512.5 KB.
__device__ float g_enc[(size_t)N_MEMS * D];
// Per-block partial weighted sums + partial exp sums (kernel B -> C).
__device__ float g_part[(size_t)NBLK_B * D];
__device__ float g_psum[NBLK_B];

// ---------------------------------------------------------------------------
// Encode body, L compile-time. 512 threads = 16 warps; warp w owns tokens
// w, w+16, ... (NT = L/16 = 4 or 2). All NT gathers in flight; norm reduces
// interleaved so the shuffle chains pipeline.
// ---------------------------------------------------------------------------
template <int L>
__device__ __forceinline__ void encode_body(
    const int* __restrict__ seq,
    const float* __restrict__ lt, const float* __restrict__ freqs,
    float* __restrict__ dst)
{
    constexpr int NW = 16;
    constexpr int NT = L / NW;

    __shared__ int   sh_idx[L];
    __shared__ float sh_w[L];
    __shared__ float sh_wred[2];
    __shared__ float sh_acc[NW][D];

    int tid  = threadIdx.x;
    int warp = tid >> 5;
    int lane = tid & 31;

    if (tid < L) {
        int idx = seq[tid];
        sh_idx[tid] = idx;
        float f = freqs[idx];
        sh_w[tid] = f;
        float ws = f * f;
        #pragma unroll
        for (int o = 16; o > 0; o >>= 1)
            ws += __shfl_xor_sync(0xffffffffu, ws, o);
        if (lane == 0) sh_wred[warp] = ws;
    }
    __syncthreads();

    float inv_wnorm = rsqrtf((L > 32) ? (sh_wred[0] + sh_wred[1]) : sh_wred[0]);

    float4 e[NT];
    int    tok[NT];
    #pragma unroll
    for (int k = 0; k < NT; k++) {
        tok[k] = warp + NW * k;
        int idx = sh_idx[tok[k]];
        e[k] = *reinterpret_cast<const float4*>(lt + (size_t)idx * D + lane * 4);
    }

    float sq[NT];
    #pragma unroll
    for (int k = 0; k < NT; k++)
        sq[k] = e[k].x * e[k].x + e[k].y * e[k].y
              + e[k].z * e[k].z + e[k].w * e[k].w;
    #pragma unroll
    for (int o = 16; o > 0; o >>= 1) {
        #pragma unroll
        for (int k = 0; k < NT; k++)
            sq[k] += __shfl_xor_sync(0xffffffffu, sq[k], o);
    }

    float4 acc = make_float4(0.0f, 0.0f, 0.0f, 0.0f);
    #pragma unroll
    for (int k = 0; k < NT; k++) {
        float n = sqrtf(sq[k]);
        float scale = (n > MAX_NORM) ? (MAX_NORM / (n + RENORM_EPS)) : 1.0f;
        float wl = sh_w[tok[k]] * inv_wnorm * scale;
        acc.x += wl * e[k].x;
        acc.y += wl * e[k].y;
        acc.z += wl * e[k].z;
        acc.w += wl * e[k].w;
    }

    sh_acc[warp][lane * 4 + 0] = acc.x;
    sh_acc[warp][lane * 4 + 1] = acc.y;
    sh_acc[warp][lane * 4 + 2] = acc.z;
    sh_acc[warp][lane * 4 + 3] = acc.w;
    __syncthreads();

    if (tid < D) {
        float s = 0.0f;
        #pragma unroll
        for (int w = 0; w < NW; w++) s += sh_acc[w][tid];
        dst[tid] = s;
    }
}

// ---------------------------------------------------------------------------
// Kernel A: encode all 1102 sequences (fully independent).
// ---------------------------------------------------------------------------
__global__ __launch_bounds__(512) void encode_all(
    const int* __restrict__ xs, const int* __restrict__ mems,
    const int* __restrict__ ys, const int* __restrict__ cands,
    const float* __restrict__ lt, const float* __restrict__ freqs,
    float* __restrict__ out)
{
    int b = blockIdx.x;
    if (b == 0) {
        encode_body<L_X>(xs, lt, freqs, g_enc);
    } else if (b <= M_MEM) {
        encode_body<L_MEM>(mems + (size_t)(b - 1) * L_MEM, lt, freqs,
                           g_enc + (size_t)b * D);
    } else if (b == M_MEM + 1) {
        encode_body<L_Y>(ys, lt, freqs, out + (size_t)OUT_ROWS * D);
    } else {
        int c = b - M_MEM - 2;
        encode_body<L_C>(cands + (size_t)c * L_C, lt, freqs,
                         out + (size_t)(OUT_ROWS + 1 + c) * D);
    }
}

// ---------------------------------------------------------------------------
// Kernel B: per-row cosine sim -> exp(sim) (no max subtraction needed: sims
// are cosines in [-1,1]) -> per-block partial weighted vector + exp sum.
// 126 blocks x 8 warps, one row per warp, all parallel.
// ---------------------------------------------------------------------------
__global__ __launch_bounds__(256) void sims_part_kernel()
{
    __shared__ float sh_part[8][D];
    __shared__ float sh_exp[8];

    int tid  = threadIdx.x;
    int warp = tid >> 5;
    int lane = tid & 31;
    int i = blockIdx.x * 8 + warp;         // logical sim index
    bool valid = (i < N_MEMS);
    int r = valid ? ((i < M_MEM) ? (i + 1) : 0) : 0;

    float4 x = *reinterpret_cast<const float4*>(&g_enc[lane * 4]);
    float4 e = *reinterpret_cast<const float4*>(&g_enc[(size_t)r * D + lane * 4]);

    float dot = e.x * x.x + e.y * x.y + e.z * x.z + e.w * x.w;
    float esq = e.x * e.x + e.y * e.y + e.z * e.z + e.w * e.w;
    float xsq = x.x * x.x + x.y * x.y + x.z * x.z + x.w * x.w;
    #pragma unroll
    for (int o = 16; o > 0; o >>= 1) {
        dot += __shfl_xor_sync(0xffffffffu, dot, o);
        esq += __shfl_xor_sync(0xffffffffu, esq, o);
        xsq += __shfl_xor_sync(0xffffffffu, xsq, o);
    }
    float nx = fmaxf(sqrtf(xsq), COS_EPS);
    float nm = fmaxf(sqrtf(esq), COS_EPS);
    float ex = valid ? expf(dot / (nx * nm)) : 0.0f;

    sh_part[warp][lane * 4 + 0] = ex * e.x;
    sh_part[warp][lane * 4 + 1] = ex * e.y;
    sh_part[warp][lane * 4 + 2] = ex * e.z;
    sh_part[warp][lane * 4 + 3] = ex * e.w;
    if (lane == 0) sh_exp[warp] = ex;
    __syncthreads();

    if (tid < D) {
        float s = 0.0f;
        #pragma unroll
        for (int w = 0; w < 8; w++) s += sh_part[w][tid];
        g_part[(size_t)blockIdx.x * D + tid] = s;
    }
    if (tid == 0) {
        float s = 0.0f;
        #pragma unroll
        for (int w = 0; w < 8; w++) s += sh_exp[w];
        g_psum[blockIdx.x] = s;
    }
}

// ---------------------------------------------------------------------------
// Kernel C: reduce 126 partials (deterministic fixed order) + write outputs.
// ---------------------------------------------------------------------------
__global__ __launch_bounds__(256) void finalize_kernel(float* __restrict__ out)
{
    __shared__ float sh_lhs[D];
    __shared__ float sh_sum;

    int tid = threadIdx.x;

    // exp-sum reduce (warp 0, fixed order within lanes then shuffle)
    if (tid < 32) {
        float s = 0.0f;
        for (int b = tid; b < NBLK_B; b += 32) s += g_psum[b];
        #pragma unroll
        for (int o = 16; o > 0; o >>= 1)
            s += __shfl_xor_sync(0xffffffffu, s, o);
        if (tid == 0) sh_sum = s;
    }

    float s = 0.0f;
    if (tid < D) {
        #pragma unroll 6
        for (int b = 0; b < NBLK_B; b++)
            s += g_part[(size_t)b * D + tid];
    }
    __syncthreads();

    if (tid < D) sh_lhs[tid] = s / sh_sum;
    __syncthreads();

    for (int j = tid; j < OUT_ROWS * D; j += 256)
        out[j] = sh_lhs[j & (D - 1)];
}

extern "C" void kernel_launch(void* const* d_in, const int* in_sizes, int n_in,
                              void* d_out, int out_size) {
    const int*   xs    = (const int*)d_in[0];
    const int*   mems  = (const int*)d_in[1];
    const int*   ys    = (const int*)d_in[2];
    const int*   cands = (const int*)d_in[3];
    const float* lt    = (const float*)d_in[4];
    const float* freqs = (const float*)d_in[5];
    float* out = (float*)d_out;

    encode_all<<<2 + M_MEM + C_N, 512>>>(xs, mems, ys, cands, lt, freqs, out);
    sims_part_kernel<<<NBLK_B, 256>>>();
    finalize_kernel<<<1, 256>>>(out);
}